// round 5
// baseline (speedup 1.0000x reference)
#include <cuda_runtime.h>

// SSIM loss, fully fused, f32x2-packed separable Gaussian convs + last-block reduce.
// Fields (a,b) and (a^2,b^2) share taps -> packed fma.rn.f32x2; a*b stays scalar.

#define IMG     512
#define W_T     64
#define H_T     32
#define RW      74          // W_T + 10
#define RH      42          // H_T + 10
#define SAB_STR 75          // float2 stride, raw (a,b) tile
#define HO_STR  65          // stride, horizontal-conv planes
#define NT      256
#define NBLK    (8 * 16 * 64)

// smem floats: AB 42*75*2 + M 42*65*2 + S 42*65*2 + P 42*65 = 19950 -> 79800 B
#define SMEM_BYTES ((2*RH*SAB_STR + 2*RH*HO_STR + 2*RH*HO_STR + RH*HO_STR) * 4)

#define SSIM_C1 0.0001f
#define SSIM_C2 0.0009f

typedef unsigned long long u64;

__device__ float        g_part[NBLK];
__device__ unsigned int g_ctr;

__device__ __forceinline__ u64 pack2(float lo, float hi) {
    u64 r; asm("mov.b64 %0,{%1,%2};" : "=l"(r) : "f"(lo), "f"(hi)); return r;
}
__device__ __forceinline__ void unpack2(u64 v, float& lo, float& hi) {
    asm("mov.b64 {%0,%1},%2;" : "=f"(lo), "=f"(hi) : "l"(v));
}
__device__ __forceinline__ u64 fma2(u64 a, u64 b, u64 c) {
    u64 d; asm("fma.rn.f32x2 %0,%1,%2,%3;" : "=l"(d) : "l"(a), "l"(b), "l"(c)); return d;
}
__device__ __forceinline__ u64 mul2(u64 a, u64 b) {
    u64 d; asm("mul.rn.f32x2 %0,%1,%2;" : "=l"(d) : "l"(a), "l"(b)); return d;
}

#define GKDEF const float gk[11] = { \
    0.00102838f, 0.00759877f, 0.03600077f, 0.10936070f, 0.21300554f, \
    0.26601173f, \
    0.21300554f, 0.10936070f, 0.03600077f, 0.00759877f, 0.00102838f }

__global__ __launch_bounds__(NT, 2) void ssim_main_kernel(
    const float* __restrict__ x_hat,
    const float* __restrict__ x,
    float* __restrict__ out,
    double inv_n)
{
    extern __shared__ float smem[];
    u64*   sAB = (u64*)smem;                          // [RH][SAB_STR] packed (a,b)
    u64*   sM  = sAB + RH * SAB_STR;                  // [RH][HO_STR] packed (mu_a,mu_b) horiz
    u64*   sS  = sM  + RH * HO_STR;                   // [RH][HO_STR] packed (Eaa,Ebb) horiz
    float* sP  = (float*)(sS + RH * HO_STR);          // [RH][HO_STR] Eab horiz

    const int tid = threadIdx.x;
    const int tx0 = blockIdx.x * W_T;
    const int ty0 = blockIdx.y * H_T;
    const long imgoff = (long)blockIdx.z * (IMG * IMG);
    const float* px  = x     + imgoff;
    const float* pxh = x_hat + imgoff;

    GKDEF;
    u64 GK2[11];
    #pragma unroll
    for (int k = 0; k < 11; k++) GK2[k] = pack2(gk[k], gk[k]);

    // ---- Stage 1: load + transform + pack + zero-pad ----
    for (int i = tid; i < RH * RW; i += NT) {
        int r = i / RW;
        int c = i - r * RW;
        int gy = ty0 + r - 5;
        int gx = tx0 + c - 5;
        float va = 0.0f, vb = 0.0f;
        if ((unsigned)gy < IMG && (unsigned)gx < IMG) {
            int gi = gy * IMG + gx;
            va = fmaf(0.5f, px[gi], 0.5f);
            vb = fmaf(0.5f, pxh[gi], 0.5f);
        }
        sAB[r * SAB_STR + c] = pack2(va, vb);
    }
    __syncthreads();

    // ---- Stage 2: horizontal 11-tap conv, 3 streams (2 packed + 1 scalar) ----
    // 42 rows x 8 segments of 8 outputs = 336 tasks
    for (int t = tid; t < RH * (W_T / 8); t += NT) {
        int r = t >> 3;
        int cbase = (t & 7) * 8;
        const u64* rab = sAB + r * SAB_STR + cbase;

        u64   accM[8], accS[8];
        float accP[8];
        #pragma unroll
        for (int o = 0; o < 8; o++) { accM[o] = 0; accS[o] = 0; accP[o] = 0.0f; }

        #pragma unroll
        for (int j = 0; j < 18; j++) {
            u64 v  = rab[j];
            u64 sq = mul2(v, v);
            float fa, fb; unpack2(v, fa, fb);
            float ab = fa * fb;
            #pragma unroll
            for (int o = 0; o < 8; o++) {
                int k = j - o;
                if (k >= 0 && k < 11) {
                    accM[o] = fma2(GK2[k], v,  accM[o]);
                    accS[o] = fma2(GK2[k], sq, accS[o]);
                    accP[o] = fmaf(gk[k], ab, accP[o]);
                }
            }
        }
        int base = r * HO_STR + cbase;
        #pragma unroll
        for (int o = 0; o < 8; o++) {
            sM[base + o] = accM[o];
            sS[base + o] = accS[o];
            sP[base + o] = accP[o];
        }
    }
    __syncthreads();

    // ---- Stage 3: vertical 11-tap conv + SSIM combine ----
    // 64 cols x 8 y-segments of 4 outputs = 512 tasks
    float lsum = 0.0f;
    for (int t = tid; t < W_T * (H_T / 4); t += NT) {
        int c  = t & (W_T - 1);
        int y0 = (t >> 6) * 4;

        u64   accM[4], accS[4];
        float accP[4];
        #pragma unroll
        for (int o = 0; o < 4; o++) { accM[o] = 0; accS[o] = 0; accP[o] = 0.0f; }

        #pragma unroll
        for (int j = 0; j < 14; j++) {
            int row = (y0 + j) * HO_STR + c;
            u64   m = sM[row];
            u64   s = sS[row];
            float p = sP[row];
            #pragma unroll
            for (int o = 0; o < 4; o++) {
                int k = j - o;
                if (k >= 0 && k < 11) {
                    accM[o] = fma2(GK2[k], m, accM[o]);
                    accS[o] = fma2(GK2[k], s, accS[o]);
                    accP[o] = fmaf(gk[k], p, accP[o]);
                }
            }
        }
        #pragma unroll
        for (int o = 0; o < 4; o++) {
            float mux, muy, Eaa, Ebb;
            unpack2(accM[o], mux, muy);
            unpack2(accS[o], Eaa, Ebb);
            float mux2 = mux * mux;
            float muy2 = muy * muy;
            float muxy = mux * muy;
            float sx  = Eaa - mux2;
            float sy  = Ebb - muy2;
            float sxy = accP[o] - muxy;
            float num = (2.0f * muxy + SSIM_C1) * (2.0f * sxy + SSIM_C2);
            float den = (mux2 + muy2 + SSIM_C1) * (sx + sy + SSIM_C2);
            lsum += __fdividef(num, den + 1e-8f);
        }
    }

    // ---- Stage 4: block reduce, publish partial, last block finalizes ----
    #pragma unroll
    for (int off = 16; off > 0; off >>= 1)
        lsum += __shfl_xor_sync(0xffffffffu, lsum, off);

    __syncthreads();
    float* wpart = smem;              // reuse
    if ((tid & 31) == 0) wpart[tid >> 5] = lsum;
    __syncthreads();

    __shared__ unsigned int s_rank;
    if (tid == 0) {
        float s = 0.0f;
        #pragma unroll
        for (int w = 0; w < NT / 32; w++) s += wpart[w];
        int blin = (blockIdx.z * gridDim.y + blockIdx.y) * gridDim.x + blockIdx.x;
        g_part[blin] = s;
        __threadfence();
        s_rank = atomicAdd(&g_ctr, 1u);
    }
    __syncthreads();

    if (s_rank == NBLK - 1) {         // last block finalizes
        __threadfence();
        double d = 0.0;
        for (int i = tid; i < NBLK; i += NT) d += (double)g_part[i];
        // reduce doubles
        #pragma unroll
        for (int off = 16; off > 0; off >>= 1)
            d += __shfl_xor_sync(0xffffffffu, d, off);
        __syncthreads();
        double* dpart = (double*)smem;
        if ((tid & 31) == 0) dpart[tid >> 5] = d;
        __syncthreads();
        if (tid == 0) {
            double s = 0.0;
            #pragma unroll
            for (int w = 0; w < NT / 32; w++) s += dpart[w];
            out[0] = (float)(1.0 - s * inv_n);
            g_ctr = 0;                // reset for next graph replay
        }
    }
}

extern "C" void kernel_launch(void* const* d_in, const int* in_sizes, int n_in,
                              void* d_out, int out_size)
{
    const float* x_hat = (const float*)d_in[0];
    const float* x     = (const float*)d_in[1];
    float* out = (float*)d_out;

    int batch = in_sizes[0] / (IMG * IMG);   // 64

    cudaFuncSetAttribute(ssim_main_kernel,
                         cudaFuncAttributeMaxDynamicSharedMemorySize, SMEM_BYTES);

    dim3 grid(IMG / W_T, IMG / H_T, batch);
    double inv_n = 1.0 / ((double)batch * IMG * IMG);
    ssim_main_kernel<<<grid, NT, SMEM_BYTES>>>(x_hat, x, out, inv_n);
}

// round 8
// speedup vs baseline: 1.2794x; 1.2794x over previous
#include <cuda_runtime.h>

// SSIM loss, fully fused scalar separable Gaussian convs (FFMA-imm taps),
// 64x16 tiles for 4 CTAs/SM, transform applied at load (reference-exact
// zero-padding of the transformed field), single kernel w/ last-block reduce.

#define IMG     512
#define W_T     64
#define H_T     16
#define RW      74          // W_T + 10
#define RH      26          // H_T + 10
#define SA_STR  75          // smem row stride, raw tiles
#define HO_STR  65          // smem row stride, horizontal-conv planes
#define NT      256
#define NBLK    (8 * 32 * 64)   // 16384 blocks

// smem floats: 2*26*75 + 5*26*65 = 3900 + 8450 = 12350 -> 49400 B (4 CTAs/SM)
#define SMEM_FLOATS (2 * RH * SA_STR + 5 * RH * HO_STR)
#define SMEM_BYTES  (SMEM_FLOATS * 4)

#define SSIM_C1 0.0001f
#define SSIM_C2 0.0009f

__device__ float        g_part[NBLK];
__device__ unsigned int g_ctr;

// Normalized 1-D Gaussian, sigma=1.5, 11 taps (outer(g,g) == reference 2-D kernel)
#define GKDEF const float gk[11] = { \
    0.00102838f, 0.00759877f, 0.03600077f, 0.10936070f, 0.21300554f, \
    0.26601173f, \
    0.21300554f, 0.10936070f, 0.03600077f, 0.00759877f, 0.00102838f }

__global__ __launch_bounds__(NT, 4) void ssim_main_kernel(
    const float* __restrict__ x_hat,
    const float* __restrict__ x,
    float* __restrict__ out,
    double inv_n)
{
    extern __shared__ float smem[];
    float* sA = smem;                       // [RH][SA_STR] a = (x+1)/2, zero-padded
    float* sB = sA + RH * SA_STR;           // [RH][SA_STR] b = (x_hat+1)/2
    float* sH = sB + RH * SA_STR;           // [5][RH][HO_STR] horiz conv of a,b,aa,bb,ab

    const int tid = threadIdx.x;
    const int tx0 = blockIdx.x * W_T;
    const int ty0 = blockIdx.y * H_T;
    const long imgoff = (long)blockIdx.z * (IMG * IMG);
    const float* px  = x     + imgoff;
    const float* pxh = x_hat + imgoff;

    // ---- Stage 1: load region (RH x RW), transform, zero-pad ----
    for (int i = tid; i < RH * RW; i += NT) {
        int r = i / RW;
        int c = i - r * RW;
        int gy = ty0 + r - 5;
        int gx = tx0 + c - 5;
        float va = 0.0f, vb = 0.0f;
        if ((unsigned)gy < IMG && (unsigned)gx < IMG) {
            int gi = gy * IMG + gx;
            va = fmaf(0.5f, px[gi], 0.5f);
            vb = fmaf(0.5f, pxh[gi], 0.5f);
        }
        sA[r * SA_STR + c] = va;
        sB[r * SA_STR + c] = vb;
    }
    __syncthreads();

    // ---- Stage 2: horizontal 11-tap conv of 5 fields ----
    // Tasks: RH rows x 8 segments (8 outputs each) = 208
    {
        GKDEF;
        for (int t = tid; t < RH * (W_T / 8); t += NT) {
            int r = t >> 3;
            int cbase = (t & 7) * 8;
            const float* ra = sA + r * SA_STR + cbase;
            const float* rb = sB + r * SA_STR + cbase;
            float acc[5][8];
            #pragma unroll
            for (int f = 0; f < 5; f++)
                #pragma unroll
                for (int o = 0; o < 8; o++) acc[f][o] = 0.0f;

            #pragma unroll
            for (int j = 0; j < 18; j++) {
                float a = ra[j];
                float b = rb[j];
                float aa = a * a, bb = b * b, ab = a * b;
                #pragma unroll
                for (int o = 0; o < 8; o++) {
                    int k = j - o;
                    if (k >= 0 && k < 11) {
                        acc[0][o] = fmaf(gk[k], a,  acc[0][o]);
                        acc[1][o] = fmaf(gk[k], b,  acc[1][o]);
                        acc[2][o] = fmaf(gk[k], aa, acc[2][o]);
                        acc[3][o] = fmaf(gk[k], bb, acc[3][o]);
                        acc[4][o] = fmaf(gk[k], ab, acc[4][o]);
                    }
                }
            }
            #pragma unroll
            for (int f = 0; f < 5; f++) {
                float* dst = sH + (f * RH + r) * HO_STR + cbase;
                #pragma unroll
                for (int o = 0; o < 8; o++) dst[o] = acc[f][o];
            }
        }
    }
    __syncthreads();

    // ---- Stage 3: vertical 11-tap conv + SSIM combine ----
    // Tasks: 64 cols x 4 y-segments (4 outputs each) = 256
    float lsum = 0.0f;
    {
        GKDEF;
        for (int t = tid; t < W_T * (H_T / 4); t += NT) {
            int c  = t & (W_T - 1);
            int y0 = (t >> 6) * 4;
            float acc[5][4];
            #pragma unroll
            for (int f = 0; f < 5; f++)
                #pragma unroll
                for (int o = 0; o < 4; o++) acc[f][o] = 0.0f;

            #pragma unroll
            for (int j = 0; j < 14; j++) {
                float v0 = sH[(0 * RH + y0 + j) * HO_STR + c];
                float v1 = sH[(1 * RH + y0 + j) * HO_STR + c];
                float v2 = sH[(2 * RH + y0 + j) * HO_STR + c];
                float v3 = sH[(3 * RH + y0 + j) * HO_STR + c];
                float v4 = sH[(4 * RH + y0 + j) * HO_STR + c];
                #pragma unroll
                for (int o = 0; o < 4; o++) {
                    int k = j - o;
                    if (k >= 0 && k < 11) {
                        acc[0][o] = fmaf(gk[k], v0, acc[0][o]);
                        acc[1][o] = fmaf(gk[k], v1, acc[1][o]);
                        acc[2][o] = fmaf(gk[k], v2, acc[2][o]);
                        acc[3][o] = fmaf(gk[k], v3, acc[3][o]);
                        acc[4][o] = fmaf(gk[k], v4, acc[4][o]);
                    }
                }
            }
            #pragma unroll
            for (int o = 0; o < 4; o++) {
                float mux = acc[0][o], muy = acc[1][o];
                float mux2 = mux * mux;
                float muy2 = muy * muy;
                float muxy = mux * muy;
                float sx  = acc[2][o] - mux2;
                float sy  = acc[3][o] - muy2;
                float sxy = acc[4][o] - muxy;
                float num = (2.0f * muxy + SSIM_C1) * (2.0f * sxy + SSIM_C2);
                float den = (mux2 + muy2 + SSIM_C1) * (sx + sy + SSIM_C2);
                lsum += __fdividef(num, den + 1e-8f);
            }
        }
    }

    // ---- Stage 4: block reduce, publish partial, last block finalizes ----
    #pragma unroll
    for (int off = 16; off > 0; off >>= 1)
        lsum += __shfl_xor_sync(0xffffffffu, lsum, off);

    __syncthreads();
    float* wpart = smem;              // reuse
    if ((tid & 31) == 0) wpart[tid >> 5] = lsum;
    __syncthreads();

    __shared__ unsigned int s_rank;
    if (tid == 0) {
        float s = 0.0f;
        #pragma unroll
        for (int w = 0; w < NT / 32; w++) s += wpart[w];
        int blin = (blockIdx.z * gridDim.y + blockIdx.y) * gridDim.x + blockIdx.x;
        g_part[blin] = s;
        __threadfence();
        s_rank = atomicAdd(&g_ctr, 1u);
    }
    __syncthreads();

    if (s_rank == NBLK - 1) {         // last block finalizes
        __threadfence();
        double d = 0.0;
        for (int i = tid; i < NBLK; i += NT) d += (double)g_part[i];
        #pragma unroll
        for (int off = 16; off > 0; off >>= 1)
            d += __shfl_xor_sync(0xffffffffu, d, off);
        __syncthreads();
        double* dpart = (double*)smem;
        if ((tid & 31) == 0) dpart[tid >> 5] = d;
        __syncthreads();
        if (tid == 0) {
            double s = 0.0;
            #pragma unroll
            for (int w = 0; w < NT / 32; w++) s += dpart[w];
            out[0] = (float)(1.0 - s * inv_n);
            g_ctr = 0;                // reset for next graph replay
        }
    }
}

extern "C" void kernel_launch(void* const* d_in, const int* in_sizes, int n_in,
                              void* d_out, int out_size)
{
    const float* x_hat = (const float*)d_in[0];
    const float* x     = (const float*)d_in[1];
    float* out = (float*)d_out;

    int batch = in_sizes[0] / (IMG * IMG);   // 64

    cudaFuncSetAttribute(ssim_main_kernel,
                         cudaFuncAttributeMaxDynamicSharedMemorySize, SMEM_BYTES);

    dim3 grid(IMG / W_T, IMG / H_T, batch);
    double inv_n = 1.0 / ((double)batch * IMG * IMG);
    ssim_main_kernel<<<grid, NT, SMEM_BYTES>>>(x_hat, x, out, inv_n);
}

// round 11
// speedup vs baseline: 1.4924x; 1.1665x over previous
#include <cuda_runtime.h>

// SSIM loss, fused separable Gaussian convs, VERTICAL-FIRST order
// (y-halo touched only by cheap raw loads, x-halo only in the 15.6%-overhead
// vertical pass). FFMA-imm taps, 64x16 tiles, 5 CTAs/SM, last-block reduce.

#define IMG     512
#define W_T     64
#define H_T     16
#define RW      74          // W_T + 10
#define RH      26          // H_T + 10
#define SA_STR  75          // smem row stride, raw tiles (RW+1)
#define SV_STR  75          // smem row stride, vertical-conv planes
#define NT      256
#define NBLK    (8 * 32 * 64)   // 16384 blocks

// smem floats: 2*26*75 + 5*16*75 = 3900 + 6000 = 9900 -> 39600 B (5 CTAs/SM)
#define SMEM_FLOATS (2 * RH * SA_STR + 5 * H_T * SV_STR)
#define SMEM_BYTES  (SMEM_FLOATS * 4)

#define SSIM_C1 0.0001f
#define SSIM_C2 0.0009f

__device__ float        g_part[NBLK];
__device__ unsigned int g_ctr;

// Normalized 1-D Gaussian, sigma=1.5, 11 taps (outer(g,g) == reference 2-D kernel)
#define GKDEF const float gk[11] = { \
    0.00102838f, 0.00759877f, 0.03600077f, 0.10936070f, 0.21300554f, \
    0.26601173f, \
    0.21300554f, 0.10936070f, 0.03600077f, 0.00759877f, 0.00102838f }

__global__ __launch_bounds__(NT, 5) void ssim_main_kernel(
    const float* __restrict__ x_hat,
    const float* __restrict__ x,
    float* __restrict__ out,
    double inv_n)
{
    extern __shared__ float smem[];
    float* sA = smem;                       // [RH][SA_STR] a = (x+1)/2, zero-padded
    float* sB = sA + RH * SA_STR;           // [RH][SA_STR] b = (x_hat+1)/2
    float* sV = sB + RH * SA_STR;           // [5][H_T][SV_STR] vertical conv of a,b,aa,bb,ab

    const int tid = threadIdx.x;
    const int tx0 = blockIdx.x * W_T;
    const int ty0 = blockIdx.y * H_T;
    const long imgoff = (long)blockIdx.z * (IMG * IMG);
    const float* px  = x     + imgoff;
    const float* pxh = x_hat + imgoff;

    // ---- Stage 1: load region (RH x RW), transform, zero-pad ----
    for (int i = tid; i < RH * RW; i += NT) {
        int r = i / RW;
        int c = i - r * RW;
        int gy = ty0 + r - 5;
        int gx = tx0 + c - 5;
        float va = 0.0f, vb = 0.0f;
        if ((unsigned)gy < IMG && (unsigned)gx < IMG) {
            int gi = gy * IMG + gx;
            va = fmaf(0.5f, px[gi], 0.5f);
            vb = fmaf(0.5f, pxh[gi], 0.5f);
        }
        sA[r * SA_STR + c] = va;
        sB[r * SA_STR + c] = vb;
    }
    __syncthreads();

    // ---- Stage A: VERTICAL 11-tap conv of 5 fields over RW cols x H_T rows ----
    // Tasks: 4 y-segments (4 outputs) x RW cols = 296 (products computed inline)
    {
        GKDEF;
        for (int t = tid; t < (H_T / 4) * RW; t += NT) {
            int seg = t / RW;
            int col = t - seg * RW;
            int y0  = seg * 4;
            const float* ca = sA + y0 * SA_STR + col;
            const float* cb = sB + y0 * SA_STR + col;

            float acc[5][4];
            #pragma unroll
            for (int f = 0; f < 5; f++)
                #pragma unroll
                for (int o = 0; o < 4; o++) acc[f][o] = 0.0f;

            #pragma unroll
            for (int j = 0; j < 14; j++) {
                float a = ca[j * SA_STR];
                float b = cb[j * SA_STR];
                float aa = a * a, bb = b * b, ab = a * b;
                #pragma unroll
                for (int o = 0; o < 4; o++) {
                    int k = j - o;
                    if (k >= 0 && k < 11) {
                        acc[0][o] = fmaf(gk[k], a,  acc[0][o]);
                        acc[1][o] = fmaf(gk[k], b,  acc[1][o]);
                        acc[2][o] = fmaf(gk[k], aa, acc[2][o]);
                        acc[3][o] = fmaf(gk[k], bb, acc[3][o]);
                        acc[4][o] = fmaf(gk[k], ab, acc[4][o]);
                    }
                }
            }
            #pragma unroll
            for (int f = 0; f < 5; f++) {
                float* dst = sV + f * (H_T * SV_STR) + y0 * SV_STR + col;
                #pragma unroll
                for (int o = 0; o < 4; o++) dst[o * SV_STR] = acc[f][o];
            }
        }
    }
    __syncthreads();

    // ---- Stage B: HORIZONTAL 11-tap conv + SSIM combine ----
    // Tasks: 256 = 16 col-segments (4 outputs) x 16 rows; low bits = row so a
    // warp's lanes stride by SV_STR (odd) -> conflict-free LDS.
    float lsum = 0.0f;
    {
        GKDEF;
        int t     = tid;
        int row   = t & (H_T - 1);
        int cbase = (t >> 4) * 4;

        float acc[5][4];
        #pragma unroll
        for (int f = 0; f < 5; f++)
            #pragma unroll
            for (int o = 0; o < 4; o++) acc[f][o] = 0.0f;

        const float* rv = sV + row * SV_STR + cbase;
        #pragma unroll
        for (int j = 0; j < 14; j++) {
            float v0 = rv[0 * (H_T * SV_STR) + j];
            float v1 = rv[1 * (H_T * SV_STR) + j];
            float v2 = rv[2 * (H_T * SV_STR) + j];
            float v3 = rv[3 * (H_T * SV_STR) + j];
            float v4 = rv[4 * (H_T * SV_STR) + j];
            #pragma unroll
            for (int o = 0; o < 4; o++) {
                int k = j - o;
                if (k >= 0 && k < 11) {
                    acc[0][o] = fmaf(gk[k], v0, acc[0][o]);
                    acc[1][o] = fmaf(gk[k], v1, acc[1][o]);
                    acc[2][o] = fmaf(gk[k], v2, acc[2][o]);
                    acc[3][o] = fmaf(gk[k], v3, acc[3][o]);
                    acc[4][o] = fmaf(gk[k], v4, acc[4][o]);
                }
            }
        }
        #pragma unroll
        for (int o = 0; o < 4; o++) {
            float mux = acc[0][o], muy = acc[1][o];
            float mux2 = mux * mux;
            float muy2 = muy * muy;
            float muxy = mux * muy;
            float sx  = acc[2][o] - mux2;
            float sy  = acc[3][o] - muy2;
            float sxy = acc[4][o] - muxy;
            float num = (2.0f * muxy + SSIM_C1) * (2.0f * sxy + SSIM_C2);
            float den = (mux2 + muy2 + SSIM_C1) * (sx + sy + SSIM_C2);
            lsum += __fdividef(num, den + 1e-8f);
        }
    }

    // ---- Stage 4: block reduce, publish partial, last block finalizes ----
    #pragma unroll
    for (int off = 16; off > 0; off >>= 1)
        lsum += __shfl_xor_sync(0xffffffffu, lsum, off);

    __syncthreads();
    float* wpart = smem;              // reuse
    if ((tid & 31) == 0) wpart[tid >> 5] = lsum;
    __syncthreads();

    __shared__ unsigned int s_rank;
    if (tid == 0) {
        float s = 0.0f;
        #pragma unroll
        for (int w = 0; w < NT / 32; w++) s += wpart[w];
        int blin = (blockIdx.z * gridDim.y + blockIdx.y) * gridDim.x + blockIdx.x;
        g_part[blin] = s;
        __threadfence();
        s_rank = atomicAdd(&g_ctr, 1u);
    }
    __syncthreads();

    if (s_rank == NBLK - 1) {         // last block finalizes
        __threadfence();
        double d = 0.0;
        for (int i = tid; i < NBLK; i += NT) d += (double)g_part[i];
        #pragma unroll
        for (int off = 16; off > 0; off >>= 1)
            d += __shfl_xor_sync(0xffffffffu, d, off);
        __syncthreads();
        double* dpart = (double*)smem;
        if ((tid & 31) == 0) dpart[tid >> 5] = d;
        __syncthreads();
        if (tid == 0) {
            double s = 0.0;
            #pragma unroll
            for (int w = 0; w < NT / 32; w++) s += dpart[w];
            out[0] = (float)(1.0 - s * inv_n);
            g_ctr = 0;                // reset for next graph replay
        }
    }
}

extern "C" void kernel_launch(void* const* d_in, const int* in_sizes, int n_in,
                              void* d_out, int out_size)
{
    const float* x_hat = (const float*)d_in[0];
    const float* x     = (const float*)d_in[1];
    float* out = (float*)d_out;

    int batch = in_sizes[0] / (IMG * IMG);   // 64

    cudaFuncSetAttribute(ssim_main_kernel,
                         cudaFuncAttributeMaxDynamicSharedMemorySize, SMEM_BYTES);

    dim3 grid(IMG / W_T, IMG / H_T, batch);
    double inv_n = 1.0 / ((double)batch * IMG * IMG);
    ssim_main_kernel<<<grid, NT, SMEM_BYTES>>>(x_hat, x, out, inv_n);
}

// round 13
// speedup vs baseline: 1.8876x; 1.2648x over previous
#include <cuda_runtime.h>

// SSIM loss, fused separable Gaussian convs, vertical-first, 4 conv fields
// {a, b, aa+bb, ab} (sum-of-squares folded pre-conv: conv is linear),
// float4 LDS in the horizontal pass, 64x16 tiles, 6 CTAs/SM target.

#define IMG     512
#define W_T     64
#define H_T     16
#define RW      74          // W_T + 10
#define RH      26          // H_T + 10
#define SA_STR  75          // raw-tile stride (odd -> conflict-free scalar col access)
#define SV_STR  76          // vertical-conv plane stride (div 4; 19 mod 8 odd -> LDS.128 ok)
#define NT      256
#define NBLK    (8 * 32 * 64)   // 16384 blocks

// smem floats: 2*26*75 + 4*16*76 = 3900 + 4864 = 8764 -> 35056 B
#define SMEM_FLOATS (2 * RH * SA_STR + 4 * H_T * SV_STR)
#define SMEM_BYTES  (SMEM_FLOATS * 4)

#define SSIM_C1 0.0001f
#define SSIM_C2 0.0009f

__device__ float        g_part[NBLK];
__device__ unsigned int g_ctr;

// Normalized 1-D Gaussian, sigma=1.5, 11 taps (outer(g,g) == reference 2-D kernel)
#define GKDEF const float gk[11] = { \
    0.00102838f, 0.00759877f, 0.03600077f, 0.10936070f, 0.21300554f, \
    0.26601173f, \
    0.21300554f, 0.10936070f, 0.03600077f, 0.00759877f, 0.00102838f }

__global__ __launch_bounds__(NT, 6) void ssim_main_kernel(
    const float* __restrict__ x_hat,
    const float* __restrict__ x,
    float* __restrict__ out,
    double inv_n)
{
    extern __shared__ float smem[];
    float* sA = smem;                       // [RH][SA_STR] a = (x+1)/2, zero-padded
    float* sB = sA + RH * SA_STR;           // [RH][SA_STR] b = (x_hat+1)/2
    float* sV = sB + RH * SA_STR;           // [4][H_T][SV_STR] vert conv of a,b,aa+bb,ab

    const int tid = threadIdx.x;
    const int tx0 = blockIdx.x * W_T;
    const int ty0 = blockIdx.y * H_T;
    const long imgoff = (long)blockIdx.z * (IMG * IMG);
    const float* px  = x     + imgoff;
    const float* pxh = x_hat + imgoff;

    // ---- Stage 1: load region (RH x RW), transform, zero-pad ----
    for (int i = tid; i < RH * RW; i += NT) {
        int r = i / RW;
        int c = i - r * RW;
        int gy = ty0 + r - 5;
        int gx = tx0 + c - 5;
        float va = 0.0f, vb = 0.0f;
        if ((unsigned)gy < IMG && (unsigned)gx < IMG) {
            int gi = gy * IMG + gx;
            va = fmaf(0.5f, px[gi], 0.5f);
            vb = fmaf(0.5f, pxh[gi], 0.5f);
        }
        sA[r * SA_STR + c] = va;
        sB[r * SA_STR + c] = vb;
    }
    __syncthreads();

    // ---- Stage A: VERTICAL 11-tap conv of 4 fields over RW cols x H_T rows ----
    // Tasks: 4 y-segments (4 outputs each) x RW cols = 296
    {
        GKDEF;
        for (int t = tid; t < (H_T / 4) * RW; t += NT) {
            int seg = t / RW;
            int col = t - seg * RW;
            int y0  = seg * 4;
            const float* ca = sA + y0 * SA_STR + col;
            const float* cb = sB + y0 * SA_STR + col;

            float acc[4][4];
            #pragma unroll
            for (int f = 0; f < 4; f++)
                #pragma unroll
                for (int o = 0; o < 4; o++) acc[f][o] = 0.0f;

            #pragma unroll
            for (int j = 0; j < 14; j++) {
                float a = ca[j * SA_STR];
                float b = cb[j * SA_STR];
                float ss = fmaf(b, b, a * a);   // aa + bb
                float ab = a * b;
                #pragma unroll
                for (int o = 0; o < 4; o++) {
                    int k = j - o;
                    if (k >= 0 && k < 11) {
                        acc[0][o] = fmaf(gk[k], a,  acc[0][o]);
                        acc[1][o] = fmaf(gk[k], b,  acc[1][o]);
                        acc[2][o] = fmaf(gk[k], ss, acc[2][o]);
                        acc[3][o] = fmaf(gk[k], ab, acc[3][o]);
                    }
                }
            }
            #pragma unroll
            for (int f = 0; f < 4; f++) {
                float* dst = sV + f * (H_T * SV_STR) + y0 * SV_STR + col;
                #pragma unroll
                for (int o = 0; o < 4; o++) dst[o * SV_STR] = acc[f][o];
            }
        }
    }
    __syncthreads();

    // ---- Stage B: HORIZONTAL 11-tap conv (float4 LDS) + SSIM combine ----
    // 256 tasks = 16 rows x 16 col-segments (4 outputs each); lanes 0-7 are
    // rows 0-7 -> LDS.128 phase-conflict-free with SV_STR=76.
    float lsum = 0.0f;
    {
        GKDEF;
        const int row   = tid & (H_T - 1);
        const int cbase = (tid >> 4) * 4;           // 0..60
        const float* base = sV + row * SV_STR + cbase;

        float acc[4][4];
        #pragma unroll
        for (int f = 0; f < 4; f++)
            #pragma unroll
            for (int o = 0; o < 4; o++) acc[f][o] = 0.0f;

        #pragma unroll
        for (int q = 0; q < 4; q++) {               // cols cbase+4q .. cbase+4q+3
            float4 v[4];
            #pragma unroll
            for (int f = 0; f < 4; f++)
                v[f] = *(const float4*)(base + f * (H_T * SV_STR) + q * 4);
            #pragma unroll
            for (int e = 0; e < 4; e++) {
                const int jj = q * 4 + e;
                if (jj < 14) {
                    float w0 = ((const float*)&v[0])[e];
                    float w1 = ((const float*)&v[1])[e];
                    float w2 = ((const float*)&v[2])[e];
                    float w3 = ((const float*)&v[3])[e];
                    #pragma unroll
                    for (int o = 0; o < 4; o++) {
                        int k = jj - o;
                        if (k >= 0 && k < 11) {
                            acc[0][o] = fmaf(gk[k], w0, acc[0][o]);
                            acc[1][o] = fmaf(gk[k], w1, acc[1][o]);
                            acc[2][o] = fmaf(gk[k], w2, acc[2][o]);
                            acc[3][o] = fmaf(gk[k], w3, acc[3][o]);
                        }
                    }
                }
            }
        }
        #pragma unroll
        for (int o = 0; o < 4; o++) {
            float mux = acc[0][o], muy = acc[1][o];
            float S   = acc[2][o];                  // E[a^2 + b^2]
            float P   = acc[3][o];                  // E[a*b]
            float mux2 = mux * mux;
            float muy2 = muy * muy;
            float muxy = mux * muy;
            float sxy  = P - muxy;
            float sxsy = S - mux2 - muy2;           // sig_x + sig_y
            float num = (2.0f * muxy + SSIM_C1) * (2.0f * sxy + SSIM_C2);
            float den = (mux2 + muy2 + SSIM_C1) * (sxsy + SSIM_C2);
            lsum += __fdividef(num, den + 1e-8f);
        }
    }

    // ---- Stage 4: block reduce, publish partial, last block finalizes ----
    #pragma unroll
    for (int off = 16; off > 0; off >>= 1)
        lsum += __shfl_xor_sync(0xffffffffu, lsum, off);

    __syncthreads();
    float* wpart = smem;              // reuse
    if ((tid & 31) == 0) wpart[tid >> 5] = lsum;
    __syncthreads();

    __shared__ unsigned int s_rank;
    if (tid == 0) {
        float s = 0.0f;
        #pragma unroll
        for (int w = 0; w < NT / 32; w++) s += wpart[w];
        int blin = (blockIdx.z * gridDim.y + blockIdx.y) * gridDim.x + blockIdx.x;
        g_part[blin] = s;
        __threadfence();
        s_rank = atomicAdd(&g_ctr, 1u);
    }
    __syncthreads();

    if (s_rank == NBLK - 1) {         // last block finalizes
        __threadfence();
        double d = 0.0;
        for (int i = tid; i < NBLK; i += NT) d += (double)g_part[i];
        #pragma unroll
        for (int off = 16; off > 0; off >>= 1)
            d += __shfl_xor_sync(0xffffffffu, d, off);
        __syncthreads();
        double* dpart = (double*)smem;
        if ((tid & 31) == 0) dpart[tid >> 5] = d;
        __syncthreads();
        if (tid == 0) {
            double s = 0.0;
            #pragma unroll
            for (int w = 0; w < NT / 32; w++) s += dpart[w];
            out[0] = (float)(1.0 - s * inv_n);
            g_ctr = 0;                // reset for next graph replay
        }
    }
}

extern "C" void kernel_launch(void* const* d_in, const int* in_sizes, int n_in,
                              void* d_out, int out_size)
{
    const float* x_hat = (const float*)d_in[0];
    const float* x     = (const float*)d_in[1];
    float* out = (float*)d_out;

    int batch = in_sizes[0] / (IMG * IMG);   // 64

    cudaFuncSetAttribute(ssim_main_kernel,
                         cudaFuncAttributeMaxDynamicSharedMemorySize, SMEM_BYTES);

    dim3 grid(IMG / W_T, IMG / H_T, batch);
    double inv_n = 1.0 / ((double)batch * IMG * IMG);
    ssim_main_kernel<<<grid, NT, SMEM_BYTES>>>(x_hat, x, out, inv_n);
}

// round 14
// speedup vs baseline: 2.3151x; 1.2264x over previous
#include <cuda_runtime.h>

// SSIM loss, fused separable Gaussian convs, vertical-first, 4 conv fields
// packed into 2 f32x2 streams: (a,b) and (aa+bb, ab). Packed fma.rn.f32x2
// halves FMA issue slots (issue-bound kernel, fma pipe was only 41% busy).
// Interleaved float2 smem layout makes packing free (LDS.64/LDS.128).

#define IMG     512
#define W_T     64
#define H_T     16
#define RW      74          // intermediate cols = W_T + 10
#define RH      26          // raw rows = H_T + 10
#define PAIRS   38          // float2 gmem pairs per raw row (76 cols, x-shifted by 1)
#define STR_AB  78          // raw-tile stride in float2 units (even -> STS.128 ok)
#define STR_V   74          // sM/sS stride in float2 units (even -> LDS.128 ok)
#define NT      256
#define NBLK    (8 * 32 * 64)   // 16384 blocks

// smem u64 words: 26*78 + 2*16*74 = 2028 + 2368 = 4396 -> 35168 B
#define SMEM_BYTES ((RH * STR_AB + 2 * H_T * STR_V) * 8)

#define SSIM_C1 0.0001f
#define SSIM_C2 0.0009f

typedef unsigned long long u64;

__device__ float        g_part[NBLK];
__device__ unsigned int g_ctr;

__device__ __forceinline__ u64 fma2(u64 a, u64 b, u64 c) {
    u64 d; asm("fma.rn.f32x2 %0,%1,%2,%3;" : "=l"(d) : "l"(a), "l"(b), "l"(c));
    return d;
}
__device__ __forceinline__ u64 pk2(float lo, float hi) {
    u64 r; asm("mov.b64 %0,{%1,%2};" : "=l"(r) : "f"(lo), "f"(hi));
    return r;
}
__device__ __forceinline__ float2 upk(u64 v) {
    float2 f; asm("mov.b64 {%0,%1},%2;" : "=f"(f.x), "=f"(f.y) : "l"(v));
    return f;
}

// broadcast-pair tap constant (compile-time folded bit pattern)
#define TAPD(g) ((((u64)__float_as_uint(g)) << 32) | (u64)__float_as_uint(g))

__global__ __launch_bounds__(NT, 5) void ssim_main_kernel(
    const float* __restrict__ x_hat,
    const float* __restrict__ x,
    float* __restrict__ out,
    double inv_n)
{
    extern __shared__ u64 smem_u[];
    u64* sAB = smem_u;                      // [RH][STR_AB]  packed (a,b) per pixel
    u64* sM  = sAB + RH * STR_AB;           // [H_T][STR_V]  packed (mu_a, mu_b) vert
    u64* sS  = sM  + H_T * STR_V;           // [H_T][STR_V]  packed (Saa+bb, Sab) vert

    const int tid = threadIdx.x;
    const int tx0 = blockIdx.x * W_T;
    const int ty0 = blockIdx.y * H_T;
    const long imgoff = (long)blockIdx.z * (IMG * IMG);
    const float* px  = x     + imgoff;
    const float* pxh = x_hat + imgoff;

    // 6 unique symmetric taps, duplicated across both f32x2 lanes
    const u64 G2[11] = {
        TAPD(0.00102838f), TAPD(0.00759877f), TAPD(0.03600077f),
        TAPD(0.10936070f), TAPD(0.21300554f), TAPD(0.26601173f),
        TAPD(0.21300554f), TAPD(0.10936070f), TAPD(0.03600077f),
        TAPD(0.00759877f), TAPD(0.00102838f)
    };

    // ---- Stage 1: float2 gmem loads, transform, interleave (a,b), zero-pad ----
    // smem col 0 = pixel x (tx0-6); pairs are even-aligned so each pair is
    // fully inside or fully outside the image.
    for (int i = tid; i < RH * PAIRS; i += NT) {
        int r = i / PAIRS;
        int c = i - r * PAIRS;
        int gy = ty0 + r - 5;
        int gx = tx0 - 6 + 2 * c;
        float4 w = make_float4(0.f, 0.f, 0.f, 0.f);
        if ((unsigned)gy < IMG && (unsigned)gx < IMG) {
            const float2 vx = *(const float2*)(px  + (long)gy * IMG + gx);
            const float2 vh = *(const float2*)(pxh + (long)gy * IMG + gx);
            w.x = fmaf(0.5f, vx.x, 0.5f);   // a, pixel gx
            w.y = fmaf(0.5f, vh.x, 0.5f);   // b, pixel gx
            w.z = fmaf(0.5f, vx.y, 0.5f);   // a, pixel gx+1
            w.w = fmaf(0.5f, vh.y, 0.5f);   // b, pixel gx+1
        }
        *(float4*)(sAB + r * STR_AB + 2 * c) = w;
    }
    __syncthreads();

    // ---- Stage A: VERTICAL 11-tap conv, 2 packed streams ----
    // Tasks: 4 y-segments (4 outputs) x RW cols = 296.
    // Intermediate col c uses raw smem col c+1 (x-shifted load).
    for (int t = tid; t < 4 * RW; t += NT) {
        int seg = t / RW;
        int col = t - seg * RW;
        int y0  = seg * 4;
        const u64* pc = sAB + y0 * STR_AB + (col + 1);

        u64 accM[4] = {0, 0, 0, 0};
        u64 accS[4] = {0, 0, 0, 0};

        #pragma unroll
        for (int j = 0; j < 14; j++) {
            u64 vab = pc[j * STR_AB];
            float2 f = upk(vab);
            float ss = fmaf(f.y, f.y, f.x * f.x);   // aa + bb
            float ab = f.x * f.y;
            u64 vsp = pk2(ss, ab);
            #pragma unroll
            for (int o = 0; o < 4; o++) {
                int k = j - o;
                if (k >= 0 && k < 11) {
                    accM[o] = fma2(G2[k], vab, accM[o]);
                    accS[o] = fma2(G2[k], vsp, accS[o]);
                }
            }
        }
        #pragma unroll
        for (int o = 0; o < 4; o++) {
            sM[(y0 + o) * STR_V + col] = accM[o];
            sS[(y0 + o) * STR_V + col] = accS[o];
        }
    }
    __syncthreads();

    // ---- Stage B: HORIZONTAL 11-tap conv (LDS.128 pairs) + SSIM combine ----
    // 256 tasks = 16 rows x 16 col-segments (4 outputs each). Row stride 74
    // float2 = 592 B -> conflict-free LDS.128 phases.
    float lsum = 0.0f;
    {
        const int row = tid & (H_T - 1);
        const int cb  = (tid >> 4) * 4;
        const ulonglong2* pM = (const ulonglong2*)(sM + row * STR_V + cb);
        const ulonglong2* pS = (const ulonglong2*)(sS + row * STR_V + cb);

        u64 accM[4] = {0, 0, 0, 0};
        u64 accS[4] = {0, 0, 0, 0};

        #pragma unroll
        for (int q = 0; q < 7; q++) {       // 14 window cols as 7 LDS.128 per plane
            ulonglong2 m2 = pM[q];
            ulonglong2 s2 = pS[q];
            #pragma unroll
            for (int e = 0; e < 2; e++) {
                int jj = 2 * q + e;
                u64 vm = e ? m2.y : m2.x;
                u64 vs = e ? s2.y : s2.x;
                #pragma unroll
                for (int o = 0; o < 4; o++) {
                    int k = jj - o;
                    if (k >= 0 && k < 11) {
                        accM[o] = fma2(G2[k], vm, accM[o]);
                        accS[o] = fma2(G2[k], vs, accS[o]);
                    }
                }
            }
        }
        #pragma unroll
        for (int o = 0; o < 4; o++) {
            float2 M = upk(accM[o]);        // (mu_x, mu_y)
            float2 S = upk(accS[o]);        // (E[aa+bb], E[ab])
            float mux = M.x, muy = M.y;
            float mux2 = mux * mux;
            float muy2 = muy * muy;
            float muxy = mux * muy;
            float sxy  = S.y - muxy;
            float sxsy = S.x - mux2 - muy2;
            float num = (2.0f * muxy + SSIM_C1) * (2.0f * sxy + SSIM_C2);
            float den = (mux2 + muy2 + SSIM_C1) * (sxsy + SSIM_C2);
            lsum += __fdividef(num, den + 1e-8f);
        }
    }

    // ---- Stage 4: block reduce, publish partial, last block finalizes ----
    #pragma unroll
    for (int off = 16; off > 0; off >>= 1)
        lsum += __shfl_xor_sync(0xffffffffu, lsum, off);

    __syncthreads();
    float* wpart = (float*)smem_u;    // reuse
    if ((tid & 31) == 0) wpart[tid >> 5] = lsum;
    __syncthreads();

    __shared__ unsigned int s_rank;
    if (tid == 0) {
        float s = 0.0f;
        #pragma unroll
        for (int w = 0; w < NT / 32; w++) s += wpart[w];
        int blin = (blockIdx.z * gridDim.y + blockIdx.y) * gridDim.x + blockIdx.x;
        g_part[blin] = s;
        __threadfence();
        s_rank = atomicAdd(&g_ctr, 1u);
    }
    __syncthreads();

    if (s_rank == NBLK - 1) {         // last block finalizes
        __threadfence();
        double d = 0.0;
        for (int i = tid; i < NBLK; i += NT) d += (double)g_part[i];
        #pragma unroll
        for (int off = 16; off > 0; off >>= 1)
            d += __shfl_xor_sync(0xffffffffu, d, off);
        __syncthreads();
        double* dpart = (double*)smem_u;
        if ((tid & 31) == 0) dpart[tid >> 5] = d;
        __syncthreads();
        if (tid == 0) {
            double s = 0.0;
            #pragma unroll
            for (int w = 0; w < NT / 32; w++) s += dpart[w];
            out[0] = (float)(1.0 - s * inv_n);
            g_ctr = 0;                // reset for next graph replay
        }
    }
}

extern "C" void kernel_launch(void* const* d_in, const int* in_sizes, int n_in,
                              void* d_out, int out_size)
{
    const float* x_hat = (const float*)d_in[0];
    const float* x     = (const float*)d_in[1];
    float* out = (float*)d_out;

    int batch = in_sizes[0] / (IMG * IMG);   // 64

    cudaFuncSetAttribute(ssim_main_kernel,
                         cudaFuncAttributeMaxDynamicSharedMemorySize, SMEM_BYTES);

    dim3 grid(IMG / W_T, IMG / H_T, batch);
    double inv_n = 1.0 / ((double)batch * IMG * IMG);
    ssim_main_kernel<<<grid, NT, SMEM_BYTES>>>(x_hat, x, out, inv_n);
}

// round 16
// speedup vs baseline: 2.5191x; 1.0881x over previous
#include <cuda_runtime.h>

// SSIM loss, fused separable Gaussian convs, vertical-first, 4 conv fields
// packed into 2 f32x2 streams: (a,b) and (aa+bb, ab). Packed fma.rn.f32x2
// halves FMA issue slots. Interleaved float2 smem layout makes packing free.
// This round: 6 CTAs/SM (regs<=42); hand-rolled div replaced by compiler
// reciprocal-multiply (previous round's 0x375 magic was wrong -> smem OOB).

#define IMG     512
#define W_T     64
#define H_T     16
#define RW      74          // intermediate cols = W_T + 10
#define RH      26          // raw rows = H_T + 10
#define PAIRS   38          // float2 gmem pairs per raw row (76 cols, x-shifted by 1)
#define STR_AB  78          // raw-tile stride in float2 units (even -> STS.128 ok)
#define STR_V   74          // sM/sS stride in float2 units (even -> LDS.128 ok)
#define NT      256
#define NBLK    (8 * 32 * 64)   // 16384 blocks

// smem u64 words: 26*78 + 2*16*74 = 2028 + 2368 = 4396 -> 35168 B (6 CTAs/SM)
#define SMEM_BYTES ((RH * STR_AB + 2 * H_T * STR_V) * 8)

#define SSIM_C1 0.0001f
#define SSIM_C2 0.0009f

typedef unsigned long long u64;

__device__ float        g_part[NBLK];
__device__ unsigned int g_ctr;

__device__ __forceinline__ u64 fma2(u64 a, u64 b, u64 c) {
    u64 d; asm("fma.rn.f32x2 %0,%1,%2,%3;" : "=l"(d) : "l"(a), "l"(b), "l"(c));
    return d;
}
__device__ __forceinline__ u64 pk2(float lo, float hi) {
    u64 r; asm("mov.b64 %0,{%1,%2};" : "=l"(r) : "f"(lo), "f"(hi));
    return r;
}
__device__ __forceinline__ float2 upk(u64 v) {
    float2 f; asm("mov.b64 {%0,%1},%2;" : "=f"(f.x), "=f"(f.y) : "l"(v));
    return f;
}

// broadcast-pair tap constant (compile-time folded bit pattern)
#define TAPD(g) ((((u64)__float_as_uint(g)) << 32) | (u64)__float_as_uint(g))

__global__ __launch_bounds__(NT, 6) void ssim_main_kernel(
    const float* __restrict__ x_hat,
    const float* __restrict__ x,
    float* __restrict__ out,
    double inv_n)
{
    extern __shared__ u64 smem_u[];
    u64* sAB = smem_u;                      // [RH][STR_AB]  packed (a,b) per pixel
    u64* sM  = sAB + RH * STR_AB;           // [H_T][STR_V]  packed (mu_a, mu_b) vert
    u64* sS  = sM  + H_T * STR_V;           // [H_T][STR_V]  packed (Saa+bb, Sab) vert

    const int tid = threadIdx.x;
    const int tx0 = blockIdx.x * W_T;
    const int ty0 = blockIdx.y * H_T;
    const long imgoff = (long)blockIdx.z * (IMG * IMG);
    const float* px  = x     + imgoff;
    const float* pxh = x_hat + imgoff;

    // 6 unique symmetric taps, duplicated across both f32x2 lanes
    const u64 G2[11] = {
        TAPD(0.00102838f), TAPD(0.00759877f), TAPD(0.03600077f),
        TAPD(0.10936070f), TAPD(0.21300554f), TAPD(0.26601173f),
        TAPD(0.21300554f), TAPD(0.10936070f), TAPD(0.03600077f),
        TAPD(0.00759877f), TAPD(0.00102838f)
    };

    // ---- Stage 1: float2 gmem loads, transform, interleave (a,b), zero-pad ----
    // smem col 0 = pixel x (tx0-6); pairs are even-aligned so each pair is
    // fully inside or fully outside the image.
    for (int i = tid; i < RH * PAIRS; i += NT) {
        int r = i / PAIRS;
        int c = i - r * PAIRS;
        int gy = ty0 + r - 5;
        int gx = tx0 - 6 + 2 * c;
        float4 w = make_float4(0.f, 0.f, 0.f, 0.f);
        if ((unsigned)gy < IMG && (unsigned)gx < IMG) {
            const float2 vx = *(const float2*)(px  + (long)gy * IMG + gx);
            const float2 vh = *(const float2*)(pxh + (long)gy * IMG + gx);
            w.x = fmaf(0.5f, vx.x, 0.5f);   // a, pixel gx
            w.y = fmaf(0.5f, vh.x, 0.5f);   // b, pixel gx
            w.z = fmaf(0.5f, vx.y, 0.5f);   // a, pixel gx+1
            w.w = fmaf(0.5f, vh.y, 0.5f);   // b, pixel gx+1
        }
        *(float4*)(sAB + r * STR_AB + 2 * c) = w;
    }
    __syncthreads();

    // ---- Stage A: VERTICAL 11-tap conv, 2 packed streams ----
    // 296 tasks = 4 y-segments (4 outputs) x RW cols, 2 strided iterations
    // per thread; t/RW lowered by the compiler to a correct recip-multiply.
    #pragma unroll
    for (int it = 0; it < 2; it++) {
        int t = tid + it * NT;
        if (t < 4 * RW) {
            int seg = t / RW;
            int col = t - seg * RW;
            int y0  = seg * 4;
            const u64* pc = sAB + y0 * STR_AB + (col + 1);

            u64 accM[4] = {0, 0, 0, 0};
            u64 accS[4] = {0, 0, 0, 0};

            #pragma unroll
            for (int j = 0; j < 14; j++) {
                u64 vab = pc[j * STR_AB];
                float2 f = upk(vab);
                float ss = fmaf(f.y, f.y, f.x * f.x);   // aa + bb
                float ab = f.x * f.y;
                u64 vsp = pk2(ss, ab);
                #pragma unroll
                for (int o = 0; o < 4; o++) {
                    int k = j - o;
                    if (k >= 0 && k < 11) {
                        accM[o] = fma2(G2[k], vab, accM[o]);
                        accS[o] = fma2(G2[k], vsp, accS[o]);
                    }
                }
            }
            #pragma unroll
            for (int o = 0; o < 4; o++) {
                sM[(y0 + o) * STR_V + col] = accM[o];
                sS[(y0 + o) * STR_V + col] = accS[o];
            }
        }
    }
    __syncthreads();

    // ---- Stage B: HORIZONTAL 11-tap conv (LDS.128 pairs) + SSIM combine ----
    // 256 tasks = 16 rows x 16 col-segments (4 outputs each). Row stride 74
    // float2 = 592 B -> conflict-free LDS.128 phases.
    float lsum = 0.0f;
    {
        const int row = tid & (H_T - 1);
        const int cb  = (tid >> 4) * 4;
        const ulonglong2* pM = (const ulonglong2*)(sM + row * STR_V + cb);
        const ulonglong2* pS = (const ulonglong2*)(sS + row * STR_V + cb);

        u64 accM[4] = {0, 0, 0, 0};
        u64 accS[4] = {0, 0, 0, 0};

        #pragma unroll
        for (int q = 0; q < 7; q++) {       // 14 window cols as 7 LDS.128 per plane
            ulonglong2 m2 = pM[q];
            ulonglong2 s2 = pS[q];
            #pragma unroll
            for (int e = 0; e < 2; e++) {
                int jj = 2 * q + e;
                u64 vm = e ? m2.y : m2.x;
                u64 vs = e ? s2.y : s2.x;
                #pragma unroll
                for (int o = 0; o < 4; o++) {
                    int k = jj - o;
                    if (k >= 0 && k < 11) {
                        accM[o] = fma2(G2[k], vm, accM[o]);
                        accS[o] = fma2(G2[k], vs, accS[o]);
                    }
                }
            }
        }
        #pragma unroll
        for (int o = 0; o < 4; o++) {
            float2 M = upk(accM[o]);        // (mu_x, mu_y)
            float2 S = upk(accS[o]);        // (E[aa+bb], E[ab])
            float mux = M.x, muy = M.y;
            float mux2 = mux * mux;
            float muy2 = muy * muy;
            float muxy = mux * muy;
            float sxy  = S.y - muxy;
            float sxsy = S.x - mux2 - muy2;
            float num = (2.0f * muxy + SSIM_C1) * (2.0f * sxy + SSIM_C2);
            float den = (mux2 + muy2 + SSIM_C1) * (sxsy + SSIM_C2);
            lsum += __fdividef(num, den + 1e-8f);
        }
    }

    // ---- Stage 4: block reduce, publish partial, last block finalizes ----
    #pragma unroll
    for (int off = 16; off > 0; off >>= 1)
        lsum += __shfl_xor_sync(0xffffffffu, lsum, off);

    __syncthreads();
    float* wpart = (float*)smem_u;    // reuse
    if ((tid & 31) == 0) wpart[tid >> 5] = lsum;
    __syncthreads();

    __shared__ unsigned int s_rank;
    if (tid == 0) {
        float s = 0.0f;
        #pragma unroll
        for (int w = 0; w < NT / 32; w++) s += wpart[w];
        int blin = (blockIdx.z * gridDim.y + blockIdx.y) * gridDim.x + blockIdx.x;
        g_part[blin] = s;
        __threadfence();
        s_rank = atomicAdd(&g_ctr, 1u);
    }
    __syncthreads();

    if (s_rank == NBLK - 1) {         // last block finalizes
        __threadfence();
        double d = 0.0;
        for (int i = tid; i < NBLK; i += NT) d += (double)g_part[i];
        #pragma unroll
        for (int off = 16; off > 0; off >>= 1)
            d += __shfl_xor_sync(0xffffffffu, d, off);
        __syncthreads();
        double* dpart = (double*)smem_u;
        if ((tid & 31) == 0) dpart[tid >> 5] = d;
        __syncthreads();
        if (tid == 0) {
            double s = 0.0;
            #pragma unroll
            for (int w = 0; w < NT / 32; w++) s += dpart[w];
            out[0] = (float)(1.0 - s * inv_n);
            g_ctr = 0;                // reset for next graph replay
        }
    }
}

extern "C" void kernel_launch(void* const* d_in, const int* in_sizes, int n_in,
                              void* d_out, int out_size)
{
    const float* x_hat = (const float*)d_in[0];
    const float* x     = (const float*)d_in[1];
    float* out = (float*)d_out;

    int batch = in_sizes[0] / (IMG * IMG);   // 64

    cudaFuncSetAttribute(ssim_main_kernel,
                         cudaFuncAttributeMaxDynamicSharedMemorySize, SMEM_BYTES);

    dim3 grid(IMG / W_T, IMG / H_T, batch);
    double inv_n = 1.0 / ((double)batch * IMG * IMG);
    ssim_main_kernel<<<grid, NT, SMEM_BYTES>>>(x_hat, x, out, inv_n);
}